// round 1
// baseline (speedup 1.0000x reference)
#include <cuda_runtime.h>

// Source map: g_src[0][c] = source for y1 channel c, g_src[1][c] = for y2.
// Encoding: bit 9 set -> source array is x2; low 9 bits -> source channel.
__device__ int g_src[2][512];

static constexpr int C = 512;
static constexpr int B = 8;
static constexpr int L = 4096;
static constexpr int TOPK = 256;          // C * (1 - 0.5)
static constexpr int L4 = L / 4;          // 1024 float4 per channel row

__global__ void build_map_kernel(const float* __restrict__ bn1,
                                 const float* __restrict__ bn2) {
    __shared__ float a1[C], a2[C];
    __shared__ int top1[C], top2[C];
    __shared__ int nt1[C], nt2[C];   // nontop channel lists (ascending); 256 used

    int c = threadIdx.x;
    a1[c] = fabsf(bn1[c]);
    a2[c] = fabsf(bn2[c]);
    __syncthreads();

    // Rank by (|bn| desc, index asc) — matches jax.lax.top_k tie semantics.
    float v1 = a1[c], v2 = a2[c];
    int r1 = 0, r2 = 0;
    #pragma unroll 8
    for (int j = 0; j < C; ++j) {
        r1 += (a1[j] > v1) || (a1[j] == v1 && j < c);
        r2 += (a2[j] > v2) || (a2[j] == v2 && j < c);
    }
    top1[c] = (r1 < TOPK);
    top2[c] = (r2 < TOPK);
    __syncthreads();

    // Position of c within the ascending-order nontop list = count of nontop j<c.
    int p1 = 0, p2 = 0;
    for (int j = 0; j < c; ++j) {
        p1 += !top1[j];
        p2 += !top2[j];
    }
    if (!top1[c]) nt1[p1] = c;
    if (!top2[c]) nt2[p2] = c;
    __syncthreads();

    // y1[:,c,:] = top1[c] ? x1[:,c,:] : x2[:, nt2[p1], :]
    g_src[0][c] = top1[c] ? c : (512 + nt2[p1]);
    // y2[:,c,:] = top2[c] ? x2[:,c,:] : x1[:, nt1[p2], :]
    g_src[1][c] = top2[c] ? (512 + c) : nt1[p2];
}

// Flat permuted copy. out layout: [which(2)][b(8)][c(512)][l(4096)] as float4.
__global__ void exchange_copy_kernel(const float4* __restrict__ x1,
                                     const float4* __restrict__ x2,
                                     float4* __restrict__ out) {
    unsigned i = blockIdx.x * blockDim.x + threadIdx.x;  // < 2*B*C*L4 = 8388608
    unsigned off   = i & (L4 - 1);
    unsigned row   = i >> 10;          // which*B*C + b*C + c
    unsigned c     = row & (C - 1);
    unsigned wb    = row >> 9;         // which*B + b
    unsigned which = wb >> 3;
    unsigned b     = wb & (B - 1);

    int s = g_src[which][c];
    const float4* __restrict__ src = (s & 512) ? x2 : x1;
    unsigned sc = (unsigned)(s & 511);

    out[i] = src[(((b << 9) + sc) << 10) + off];
}

extern "C" void kernel_launch(void* const* d_in, const int* in_sizes, int n_in,
                              void* d_out, int out_size) {
    const float* x1  = (const float*)d_in[0];
    const float* x2  = (const float*)d_in[1];
    const float* bn1 = (const float*)d_in[2];
    const float* bn2 = (const float*)d_in[3];

    build_map_kernel<<<1, C>>>(bn1, bn2);

    const unsigned total4 = 2u * B * C * L4;   // 8,388,608 float4
    const int threads = 256;
    const unsigned blocks = total4 / threads;  // 32768
    exchange_copy_kernel<<<blocks, threads>>>((const float4*)x1,
                                              (const float4*)x2,
                                              (float4*)d_out);
}

// round 2
// speedup vs baseline: 1.1770x; 1.1770x over previous
#include <cuda_runtime.h>

// Source map: g_src[0][c] = source for y1 channel c, g_src[1][c] = for y2.
// Encoding: bit 9 set -> source array is x2; low 9 bits -> source channel.
__device__ int g_src[2][512];

static constexpr int C = 512;
static constexpr int B = 8;
static constexpr int L = 4096;
static constexpr int TOPK = 256;          // C * (1 - 0.5)
static constexpr int L4 = L / 4;          // 1024 float4 per channel row

__global__ void build_map_kernel(const float* __restrict__ bn1,
                                 const float* __restrict__ bn2) {
    __shared__ float2 a[C];                 // (|bn1[c]|, |bn2[c]|) interleaved
    __shared__ unsigned m1s[16], m2s[16];   // per-warp nontop ballots
    __shared__ int nt1[C], nt2[C];          // nontop lists (ascending); 256 used

    int c = threadIdx.x;
    a[c] = make_float2(fabsf(bn1[c]), fabsf(bn2[c]));
    __syncthreads();

    // Rank by (|bn| desc, index asc) — matches jax.lax.top_k tie semantics.
    // float4 reads over the interleaved array: 1 LDS.128 covers 2 j's of both arrays.
    float v1 = a[c].x, v2 = a[c].y;
    int r1 = 0, r2 = 0;
    const float4* a4 = (const float4*)a;
    #pragma unroll 8
    for (int j4 = 0; j4 < C / 2; ++j4) {
        float4 t = a4[j4];
        int j0 = 2 * j4, j1 = 2 * j4 + 1;
        r1 += (t.x > v1) || (t.x == v1 && j0 < c);
        r2 += (t.y > v2) || (t.y == v2 && j0 < c);
        r1 += (t.z > v1) || (t.z == v1 && j1 < c);
        r2 += (t.w > v2) || (t.w == v2 && j1 < c);
    }
    bool top1 = (r1 < TOPK);
    bool top2 = (r2 < TOPK);

    // Ballot/popc block scan: position of c within ascending nontop list.
    unsigned b1 = __ballot_sync(0xFFFFFFFFu, !top1);
    unsigned b2 = __ballot_sync(0xFFFFFFFFu, !top2);
    int warp = c >> 5, lane = c & 31;
    if (lane == 0) { m1s[warp] = b1; m2s[warp] = b2; }
    __syncthreads();

    int p1 = 0, p2 = 0;
    #pragma unroll
    for (int w = 0; w < 16; ++w) {
        if (w < warp) { p1 += __popc(m1s[w]); p2 += __popc(m2s[w]); }
    }
    unsigned lt = (1u << lane) - 1u;
    p1 += __popc(b1 & lt);
    p2 += __popc(b2 & lt);

    if (!top1) nt1[p1] = c;
    if (!top2) nt2[p2] = c;
    __syncthreads();

    // y1[:,c,:] = top1 ? x1[:,c,:] : x2[:, nontop2[p1], :]
    g_src[0][c] = top1 ? c : (512 + nt2[p1]);
    // y2[:,c,:] = top2 ? x2[:,c,:] : x1[:, nontop1[p2], :]
    g_src[1][c] = top2 ? (512 + c) : nt1[p2];
}

// One block per 16 KiB channel row. 256 threads x 4 float4 each, batched
// loads for MLP=4. out layout: [which(2)][b(8)][c(512)][l(4096)].
__global__ void __launch_bounds__(256)
exchange_copy_kernel(const float4* __restrict__ x1,
                     const float4* __restrict__ x2,
                     float4* __restrict__ out) {
    unsigned row   = blockIdx.x;           // which*4096 + b*512 + c
    unsigned c     = row & (C - 1);
    unsigned wb    = row >> 9;
    unsigned which = wb >> 3;
    unsigned b     = wb & (B - 1);

    int s = g_src[which][c];
    const float4* __restrict__ src = (s & 512) ? x2 : x1;
    unsigned sbase = (((b << 9) + (unsigned)(s & 511)) << 10) + threadIdx.x;
    unsigned dbase = (row << 10) + threadIdx.x;

    float4 v0 = __ldcs(src + sbase);
    float4 v1 = __ldcs(src + sbase + 256);
    float4 v2 = __ldcs(src + sbase + 512);
    float4 v3 = __ldcs(src + sbase + 768);
    __stcs(out + dbase,       v0);
    __stcs(out + dbase + 256, v1);
    __stcs(out + dbase + 512, v2);
    __stcs(out + dbase + 768, v3);
}

extern "C" void kernel_launch(void* const* d_in, const int* in_sizes, int n_in,
                              void* d_out, int out_size) {
    const float* x1  = (const float*)d_in[0];
    const float* x2  = (const float*)d_in[1];
    const float* bn1 = (const float*)d_in[2];
    const float* bn2 = (const float*)d_in[3];

    build_map_kernel<<<1, C>>>(bn1, bn2);

    const unsigned rows = 2u * B * C;      // 8192 channel rows
    exchange_copy_kernel<<<rows, 256>>>((const float4*)x1,
                                        (const float4*)x2,
                                        (float4*)d_out);
}

// round 3
// speedup vs baseline: 1.3103x; 1.1133x over previous
#include <cuda_runtime.h>

static constexpr int C = 512;
static constexpr int B = 8;
static constexpr int L = 4096;
static constexpr int TOPK = 256;          // C * (1 - EXCHANGE_RATIO)
static constexpr int L4 = L / 4;          // 1024 float4 per channel row

// Per-array tables, filled by build_map_kernel (block a handles bn_{a+1}):
//   g_tp[a][c] = -1 if channel c is in top-k of |bn_a|, else its position in
//                the ascending-index list of non-top channels (0..255).
//   g_nt[a][k] = k-th non-top channel of array a (ascending index order).
__device__ int g_tp[2][C];
__device__ int g_nt[2][TOPK];

__global__ void build_map_kernel(const float* __restrict__ bn1,
                                 const float* __restrict__ bn2) {
    __shared__ unsigned long long key[C];
    __shared__ unsigned ballots[16];

    int a = blockIdx.x;                       // 0 -> bn1, 1 -> bn2
    const float* bn = a ? bn2 : bn1;
    int c = threadIdx.x;

    // Non-negative floats order like their bit patterns (unsigned).
    // key = (bits << 10) | (1023 - c): equal values -> smaller index wins
    // (ranks higher), matching jax.lax.top_k tie semantics.
    unsigned bits = __float_as_uint(fabsf(bn[c]));
    unsigned long long k = ((unsigned long long)bits << 10) | (unsigned)(1023 - c);
    key[c] = k;
    __syncthreads();

    // rank(c) = #{ j : key_j > key_c }  (self-compare is false)
    int r = 0;
    const ulonglong2* k2 = (const ulonglong2*)key;
    #pragma unroll 8
    for (int j = 0; j < C / 2; ++j) {
        ulonglong2 t = k2[j];
        r += (t.x > k);
        r += (t.y > k);
    }
    bool nontop = (r >= TOPK);

    // Ballot/popc block scan: position among non-top channels, ascending index.
    unsigned bal = __ballot_sync(0xFFFFFFFFu, nontop);
    int warp = c >> 5, lane = c & 31;
    if (lane == 0) ballots[warp] = bal;
    __syncthreads();

    int p = 0;
    #pragma unroll
    for (int w = 0; w < 16; ++w)
        if (w < warp) p += __popc(ballots[w]);
    p += __popc(bal & ((1u << lane) - 1u));

    if (nontop) g_nt[a][p] = c;
    g_tp[a][c] = nontop ? p : -1;
}

// One block per 16 KiB channel row; 128 threads x 8 float4 in flight.
// out layout: [which(2)][b(8)][c(512)][l(4096)].
// Source resolution: y_{which}[:,c,:] keeps x_{which} if c is top in bn_{which},
// else takes x_{other}[:, nt_other[pos_which(c)], :].
__global__ void __launch_bounds__(128)
exchange_copy_kernel(const float4* __restrict__ x1,
                     const float4* __restrict__ x2,
                     float4* __restrict__ out) {
    unsigned row   = blockIdx.x;           // which*4096 + b*512 + c
    unsigned c     = row & (C - 1);
    unsigned wb    = row >> 9;
    unsigned which = wb >> 3;
    unsigned b     = wb & (B - 1);

    int tp = g_tp[which][c];
    unsigned o = which ^ 1u;
    int s = (tp < 0) ? (int)((which << 9) | c)
                     : (int)((o << 9) | (unsigned)g_nt[o][tp]);

    const float4* __restrict__ src = (s & 512) ? x2 : x1;
    unsigned sbase = (((b << 9) + (unsigned)(s & 511)) << 10) + threadIdx.x;
    unsigned dbase = (row << 10) + threadIdx.x;

    float4 v0 = __ldcs(src + sbase);
    float4 v1 = __ldcs(src + sbase + 128);
    float4 v2 = __ldcs(src + sbase + 256);
    float4 v3 = __ldcs(src + sbase + 384);
    float4 v4 = __ldcs(src + sbase + 512);
    float4 v5 = __ldcs(src + sbase + 640);
    float4 v6 = __ldcs(src + sbase + 768);
    float4 v7 = __ldcs(src + sbase + 896);
    __stcs(out + dbase,       v0);
    __stcs(out + dbase + 128, v1);
    __stcs(out + dbase + 256, v2);
    __stcs(out + dbase + 384, v3);
    __stcs(out + dbase + 512, v4);
    __stcs(out + dbase + 640, v5);
    __stcs(out + dbase + 768, v6);
    __stcs(out + dbase + 896, v7);
}

extern "C" void kernel_launch(void* const* d_in, const int* in_sizes, int n_in,
                              void* d_out, int out_size) {
    const float* x1  = (const float*)d_in[0];
    const float* x2  = (const float*)d_in[1];
    const float* bn1 = (const float*)d_in[2];
    const float* bn2 = (const float*)d_in[3];

    build_map_kernel<<<2, C>>>(bn1, bn2);

    const unsigned rows = 2u * B * C;      // 8192 channel rows
    exchange_copy_kernel<<<rows, 128>>>((const float4*)x1,
                                        (const float4*)x2,
                                        (float4*)d_out);
}

// round 5
// speedup vs baseline: 1.3176x; 1.0056x over previous
#include <cuda_runtime.h>

static constexpr int C = 512;
static constexpr int B = 8;
static constexpr int L = 4096;
static constexpr int TOPK = 256;          // C * (1 - EXCHANGE_RATIO)
static constexpr int L4 = L / 4;          // 1024 float4 per channel row

// Per-array tables, filled by build_map_kernel (block a handles bn_{a+1}):
//   g_tp[a][c] = -1 if channel c is in top-k of |bn_a|, else its position in
//                the ascending-index list of non-top channels (0..255).
//   g_nt[a][k] = k-th non-top channel of array a (ascending index order).
__device__ int g_tp[2][C];
__device__ int g_nt[2][TOPK];

__global__ void build_map_kernel(const float* __restrict__ bn1,
                                 const float* __restrict__ bn2) {
    // Let the dependent (copy) grid start launching immediately; it will
    // block in cudaGridDependencySynchronize() until this grid completes.
    cudaTriggerProgrammaticLaunchCompletion();

    __shared__ unsigned long long key[C];
    __shared__ unsigned ballots[16];

    int a = blockIdx.x;                       // 0 -> bn1, 1 -> bn2
    const float* bn = a ? bn2 : bn1;
    int c = threadIdx.x;

    // Non-negative floats order like their bit patterns (unsigned).
    // key = (bits << 10) | (1023 - c): equal values -> smaller index wins
    // (ranks higher), matching jax.lax.top_k tie semantics.
    unsigned bits = __float_as_uint(fabsf(bn[c]));
    unsigned long long k = ((unsigned long long)bits << 10) | (unsigned)(1023 - c);
    key[c] = k;
    __syncthreads();

    // rank(c) = #{ j : key_j > key_c }  (self-compare is false)
    int r = 0;
    const ulonglong2* k2 = (const ulonglong2*)key;
    #pragma unroll 8
    for (int j = 0; j < C / 2; ++j) {
        ulonglong2 t = k2[j];
        r += (t.x > k);
        r += (t.y > k);
    }
    bool nontop = (r >= TOPK);

    // Ballot/popc block scan: position among non-top channels, ascending index.
    unsigned bal = __ballot_sync(0xFFFFFFFFu, nontop);
    int warp = c >> 5, lane = c & 31;
    if (lane == 0) ballots[warp] = bal;
    __syncthreads();

    int p = 0;
    #pragma unroll
    for (int w = 0; w < 16; ++w)
        if (w < warp) p += __popc(ballots[w]);
    p += __popc(bal & ((1u << lane) - 1u));

    if (nontop) g_nt[a][p] = c;
    g_tp[a][c] = nontop ? p : -1;
}

// One block per 16 KiB channel row; 256 threads x 4 float4 in flight
// (measured-best copy config). out layout: [which(2)][b(8)][c(512)][l(4096)].
// y_{which}[:,c,:] keeps x_{which} if c is top in bn_{which}, else takes
// x_{other}[:, nt_other[pos_which(c)], :].
__global__ void __launch_bounds__(256)
exchange_copy_kernel(const float4* __restrict__ x1,
                     const float4* __restrict__ x2,
                     float4* __restrict__ out) {
    // Map-independent index math first (overlaps with the map kernel).
    unsigned row   = blockIdx.x;           // which*4096 + b*512 + c
    unsigned c     = row & (C - 1);
    unsigned wb    = row >> 9;
    unsigned which = wb >> 3;
    unsigned b     = wb & (B - 1);
    unsigned dbase = (row << 10) + threadIdx.x;

    // Wait for build_map_kernel's tables to be complete and visible.
    cudaGridDependencySynchronize();

    int tp = g_tp[which][c];
    unsigned o = which ^ 1u;
    int s = (tp < 0) ? (int)((which << 9) | c)
                     : (int)((o << 9) | (unsigned)g_nt[o][tp]);

    const float4* __restrict__ src = (s & 512) ? x2 : x1;
    unsigned sbase = (((b << 9) + (unsigned)(s & 511)) << 10) + threadIdx.x;

    float4 v0 = __ldcs(src + sbase);
    float4 v1 = __ldcs(src + sbase + 256);
    float4 v2 = __ldcs(src + sbase + 512);
    float4 v3 = __ldcs(src + sbase + 768);
    __stcs(out + dbase,       v0);
    __stcs(out + dbase + 256, v1);
    __stcs(out + dbase + 512, v2);
    __stcs(out + dbase + 768, v3);
}

extern "C" void kernel_launch(void* const* d_in, const int* in_sizes, int n_in,
                              void* d_out, int out_size) {
    const float* x1  = (const float*)d_in[0];
    const float* x2  = (const float*)d_in[1];
    const float* bn1 = (const float*)d_in[2];
    const float* bn2 = (const float*)d_in[3];

    build_map_kernel<<<2, C>>>(bn1, bn2);

    // Programmatic dependent launch: copy grid launches while map runs.
    cudaLaunchConfig_t cfg = {};
    cfg.gridDim = dim3(2u * B * C);        // 8192 channel rows
    cfg.blockDim = dim3(256);
    cfg.dynamicSmemBytes = 0;
    cfg.stream = 0;
    cudaLaunchAttribute attr[1];
    attr[0].id = cudaLaunchAttributeProgrammaticStreamSerialization;
    attr[0].val.programmaticStreamSerializationAllowed = 1;
    cfg.attrs = attr;
    cfg.numAttrs = 1;
    cudaLaunchKernelEx(&cfg, exchange_copy_kernel,
                       (const float4*)x1, (const float4*)x2, (float4*)d_out);
}